// round 2
// baseline (speedup 1.0000x reference)
#include <cuda_runtime.h>

#define NROWS 512
#define DDIM  512

// Scratch (allocation-free rule: __device__ globals)
__device__ float g_inv[NROWS];
__device__ float g_cos[NROWS * NROWS];
__device__ int   g_idx32;   // 1 if indices buffer is int32, 0 if int64

// ---------------------------------------------------------------------------
// Kernel 1: per-row inverse norms (clamped at eps). Block 0 also zeroes the
// output scalar and probes the indices dtype.
// grid = 512 blocks, 128 threads each.
// ---------------------------------------------------------------------------
__global__ void norm_kernel(const float* __restrict__ embs,
                            const int* __restrict__ idx32view,
                            float* __restrict__ out) {
    const int i = blockIdx.x;
    const int t = threadIdx.x;
    const float* row = embs + i * DDIM;

    float s = 0.f;
    for (int k = t; k < DDIM; k += 128) {
        float v = row[k];
        s += v * v;
    }
#pragma unroll
    for (int o = 16; o; o >>= 1) s += __shfl_xor_sync(0xffffffffu, s, o);

    __shared__ float ws[4];
    __shared__ int   fl[4];
    if ((t & 31) == 0) ws[t >> 5] = s;

    if (i == 0) {
        // Dtype probe: odd int32 positions within the first 2048 bytes.
        // int64 layout -> all zero (high words of values in [0,64)).
        // int32 layout -> real class IDs, essentially never all zero.
        int f = 0;
        for (int p = t; p < 256; p += 128) f |= idx32view[2 * p + 1];
#pragma unroll
        for (int o = 16; o; o >>= 1) f |= __shfl_xor_sync(0xffffffffu, f, o);
        if ((t & 31) == 0) fl[t >> 5] = f;
    }
    __syncthreads();

    if (t == 0) {
        float tot = ws[0] + ws[1] + ws[2] + ws[3];
        float nrm = fmaxf(sqrtf(tot), 1e-8f);
        g_inv[i] = 1.0f / nrm;
        if (i == 0) {
            g_idx32 = ((fl[0] | fl[1] | fl[2] | fl[3]) != 0) ? 1 : 0;
            *out = 0.0f;  // zero the scalar accumulator
        }
    }
}

// ---------------------------------------------------------------------------
// Kernel 2: cos[i][j] = dot(E_i, E_j) * inv_i * inv_j  (fp32 tiled GEMM)
// grid = (16,16), block = (32,32). 32x32 output tile, K chunks of 32.
// ---------------------------------------------------------------------------
__global__ void cos_kernel(const float* __restrict__ embs) {
    __shared__ float As[32][33];
    __shared__ float Bs[32][33];

    const int tx = threadIdx.x;
    const int ty = threadIdx.y;
    const int row = blockIdx.y * 32 + ty;
    const int col = blockIdx.x * 32 + tx;

    float acc = 0.f;
    for (int kk = 0; kk < DDIM; kk += 32) {
        As[ty][tx] = embs[row * DDIM + kk + tx];
        Bs[ty][tx] = embs[(blockIdx.x * 32 + ty) * DDIM + kk + tx];
        __syncthreads();
#pragma unroll
        for (int k = 0; k < 32; k++) acc += As[ty][k] * Bs[tx][k];
        __syncthreads();
    }
    g_cos[row * NROWS + col] = acc * g_inv[row] * g_inv[col];
}

// ---------------------------------------------------------------------------
// Kernel 3: triplet sum. One block per anchor i (512 blocks, 256 threads).
// Partition cos row i (j>i) into pos/neg value lists in shared, then flat
// pos x neg pair loop of relu(c_neg - c_pos + margin). Block-reduce +
// atomicAdd into the scalar output.
// ---------------------------------------------------------------------------
__global__ void triplet_kernel(const void* __restrict__ idxraw,
                               float* __restrict__ out) {
    const int i = blockIdx.x;
    const int t = threadIdx.x;  // 256 threads

    __shared__ float posv[NROWS];
    __shared__ float negv[NROWS];
    __shared__ int cnt[2];  // [0]=npos, [1]=nneg

    if (t < 2) cnt[t] = 0;
    __syncthreads();

    const int is32 = g_idx32;
    const int* __restrict__ i32 = (const int*)idxraw;
    const long long* __restrict__ i64 = (const long long*)idxraw;

    const int ci = is32 ? i32[i] : (int)i64[i];
    for (int j = i + 1 + t; j < NROWS; j += 256) {
        int cj = is32 ? i32[j] : (int)i64[j];
        float c = g_cos[i * NROWS + j];
        if (cj == ci) {
            int p = atomicAdd(&cnt[0], 1);
            posv[p] = c;
        } else {
            int p = atomicAdd(&cnt[1], 1);
            negv[p] = c;
        }
    }
    __syncthreads();

    const int np = cnt[0];
    const int nn = cnt[1];
    const int total = np * nn;

    float s = 0.f;
    for (int p = t; p < total; p += 256) {
        int pi = p / nn;
        int ni = p - pi * nn;
        s += fmaxf(negv[ni] - posv[pi] + 1.0f, 0.0f);
    }

#pragma unroll
    for (int o = 16; o; o >>= 1) s += __shfl_xor_sync(0xffffffffu, s, o);

    __shared__ float ws[8];
    if ((t & 31) == 0) ws[t >> 5] = s;
    __syncthreads();
    if (t < 8) {
        float v = ws[t];
#pragma unroll
        for (int o = 4; o; o >>= 1) v += __shfl_xor_sync(0xffu, v, o);
        if (t == 0) atomicAdd(out, v);
    }
}

extern "C" void kernel_launch(void* const* d_in, const int* in_sizes, int n_in,
                              void* d_out, int out_size) {
    const float* embs = (const float*)d_in[0];
    const void*  indices = d_in[1];
    float* out = (float*)d_out;

    norm_kernel<<<NROWS, 128>>>(embs, (const int*)indices, out);

    dim3 blk(32, 32);
    dim3 grd(NROWS / 32, NROWS / 32);
    cos_kernel<<<grd, blk>>>(embs);

    triplet_kernel<<<NROWS, 256>>>(indices, out);
}

// round 4
// speedup vs baseline: 1.7816x; 1.7816x over previous
#include <cuda_runtime.h>

#define NROWS 512
#define DDIM  512
#define NTILE 16          // 512/32 tiles per dim
#define UPPER_TILES 136   // NTILE*(NTILE+1)/2

// Scratch (allocation-free rule: __device__ globals)
__device__ float g_dot[NROWS * NROWS];  // raw dot products (upper triangle + diag)
__device__ int   g_idx32;               // 1 if indices buffer is int32, 0 if int64

// ---------------------------------------------------------------------------
// Kernel 1: raw dot-product GEMM, upper-triangle tiles only (bx >= by).
// 136 blocks x 256 threads (16x16), 32x32 tile, 2x2 micro-tile, K-chunk 32.
// A/B staged transposed [k][m] so the inner loop is 2x LDS.64 + 4 FFMA.
// Block 0 also zeroes the output scalar and probes the indices dtype.
// ---------------------------------------------------------------------------
__global__ void dot_kernel(const float* __restrict__ embs,
                           const int* __restrict__ idx32view,
                           float* __restrict__ out) {
    // Decode linear block id -> (by, bx) with bx >= by
    int rem = blockIdx.x;
    int by = 0;
    while (rem >= NTILE - by) { rem -= NTILE - by; by++; }
    const int bx = by + rem;

    const int tid = threadIdx.x;          // 0..255
    const int tx = tid & 15;
    const int ty = tid >> 4;

    __shared__ float Ash[32][34];         // [k][m], pad 34: float2-aligned + conflict-free
    __shared__ float Bsh[32][34];

    float a00 = 0.f, a01 = 0.f, a10 = 0.f, a11 = 0.f;

    const int m0 = by * 32;
    const int n0 = bx * 32;

    for (int kk = 0; kk < DDIM; kk += 32) {
#pragma unroll
        for (int e = 0; e < 4; e++) {
            int li = tid + e * 256;       // 0..1023
            int m = li >> 5;
            int k = li & 31;
            Ash[k][m] = embs[(m0 + m) * DDIM + kk + k];
            Bsh[k][m] = embs[(n0 + m) * DDIM + kk + k];
        }
        __syncthreads();
#pragma unroll
        for (int k = 0; k < 32; k++) {
            float2 a = *(const float2*)&Ash[k][2 * ty];
            float2 b = *(const float2*)&Bsh[k][2 * tx];
            a00 += a.x * b.x; a01 += a.x * b.y;
            a10 += a.y * b.x; a11 += a.y * b.y;
        }
        __syncthreads();
    }

    const int row0 = m0 + 2 * ty;
    const int col0 = n0 + 2 * tx;
    *(float2*)&g_dot[row0 * NROWS + col0]       = make_float2(a00, a01);
    *(float2*)&g_dot[(row0 + 1) * NROWS + col0] = make_float2(a10, a11);

    if (blockIdx.x == 0) {
        // Dtype probe: odd int32 positions within the first 2048 bytes.
        // int64 layout -> all zero (high words of values in [0,64)).
        // int32 layout -> real class IDs, essentially never all zero.
        __shared__ int fl;
        if (tid == 0) { fl = 0; *out = 0.0f; }
        __syncthreads();
        if (idx32view[2 * tid + 1] != 0) atomicOr(&fl, 1);
        __syncthreads();
        if (tid == 0) g_idx32 = fl;
    }
}

// ---------------------------------------------------------------------------
// Kernel 2: triplet sum, warp-per-anchor. 64 blocks x 256 threads.
// Per block: cache inv-norms (from GEMM diagonal) + class IDs in shared.
// Per warp (anchor i): pass 1 compacts positive cos values with a
// WARP-UNIFORM ballot loop (jbase is lane-independent; lane validity is a
// predicate inside the iteration -> no divergent collectives). Pass 2
// streams negatives vs the positive list. One atomicAdd per warp.
// ---------------------------------------------------------------------------
__global__ void triplet_kernel(const void* __restrict__ idxraw,
                               float* __restrict__ out) {
    const int tid  = threadIdx.x;
    const int w    = tid >> 5;            // warp 0..7
    const int lane = tid & 31;

    __shared__ float s_inv[NROWS];
    __shared__ int   s_cls[NROWS];
    __shared__ float s_pos[8][32];        // positives per anchor (tiny: ~4 expected)

    const int is32 = g_idx32;
    const int* __restrict__ i32 = (const int*)idxraw;
    const long long* __restrict__ i64 = (const long long*)idxraw;

    for (int r = tid; r < NROWS; r += 256) {
        float d = g_dot[r * NROWS + r];
        s_inv[r] = 1.0f / fmaxf(sqrtf(d), 1e-8f);
        s_cls[r] = is32 ? i32[r] : (int)i64[r];
    }
    __syncthreads();

    const int i = blockIdx.x * 8 + w;     // anchor
    const int   ci   = s_cls[i];
    const float invi = s_inv[i];
    const float* __restrict__ rowi = &g_dot[i * NROWS];

    // Pass 1: compact positives (same class, j > i). Uniform trip count:
    // loop bound depends only on jbase, all 32 lanes hit every ballot.
    int np = 0;
    for (int jbase = i + 1; jbase < NROWS; jbase += 32) {
        int j = jbase + lane;
        bool match = (j < NROWS) && (s_cls[j] == ci);
        unsigned mask = __ballot_sync(0xffffffffu, match);
        if (match) {
            int off = np + __popc(mask & ((1u << lane) - 1u));
            if (off < 32) s_pos[w][off] = rowi[j] * invi * s_inv[j];
        }
        np += __popc(mask);
    }
    if (np > 32) np = 32;   // capacity guard (expected np ~ 4, P(>32) ~ 0)
    __syncwarp();

    // Pass 2: stream negatives against the positive list
    float s = 0.f;
    for (int jbase = i + 1; jbase < NROWS; jbase += 32) {
        int j = jbase + lane;
        if (j < NROWS && s_cls[j] != ci) {
            float c = rowi[j] * invi * s_inv[j];
            for (int p = 0; p < np; p++)
                s += fmaxf(c - s_pos[w][p] + 1.0f, 0.0f);
        }
    }

#pragma unroll
    for (int o = 16; o; o >>= 1) s += __shfl_xor_sync(0xffffffffu, s, o);
    if (lane == 0) atomicAdd(out, s);
}

extern "C" void kernel_launch(void* const* d_in, const int* in_sizes, int n_in,
                              void* d_out, int out_size) {
    const float* embs = (const float*)d_in[0];
    const void*  indices = d_in[1];
    float* out = (float*)d_out;

    dot_kernel<<<UPPER_TILES, 256>>>(embs, (const int*)indices, out);
    triplet_kernel<<<NROWS / 8, 256>>>(indices, out);
}

// round 5
// speedup vs baseline: 2.0816x; 1.1684x over previous
#include <cuda_runtime.h>

#define NROWS 512
#define DDIM  512
#define NTILE 16          // 512/32 tiles per dim
#define UPPER_TILES 136   // NTILE*(NTILE+1)/2

// Scratch (allocation-free rule: __device__ globals)
__device__ float g_dot[NROWS * NROWS];  // raw dot products (upper triangle + diag)
__device__ float g_inv[NROWS];          // 1/max(norm,eps), written by diagonal tiles
__device__ int   g_idx32;               // 1 if indices buffer is int32, 0 if int64

// ---------------------------------------------------------------------------
// Kernel 1: raw dot-product GEMM, upper-triangle tiles only (bx >= by).
// 136 blocks x 256 threads (16x16), 32x32 tile, 2x2 micro-tile, K-chunk 32.
// Diagonal tiles (bx==by) also emit inverse norms from their diagonal.
// Block 0 zeroes the output scalar and probes the indices dtype.
// ---------------------------------------------------------------------------
__global__ void dot_kernel(const float* __restrict__ embs,
                           const int* __restrict__ idx32view,
                           float* __restrict__ out) {
    // Decode linear block id -> (by, bx) with bx >= by
    int rem = blockIdx.x;
    int by = 0;
    while (rem >= NTILE - by) { rem -= NTILE - by; by++; }
    const int bx = by + rem;

    const int tid = threadIdx.x;          // 0..255
    const int tx = tid & 15;
    const int ty = tid >> 4;

    __shared__ float Ash[32][34];         // [k][m], pad 34: float2-aligned + conflict-free
    __shared__ float Bsh[32][34];

    float a00 = 0.f, a01 = 0.f, a10 = 0.f, a11 = 0.f;

    const int m0 = by * 32;
    const int n0 = bx * 32;

    for (int kk = 0; kk < DDIM; kk += 32) {
#pragma unroll
        for (int e = 0; e < 4; e++) {
            int li = tid + e * 256;       // 0..1023
            int m = li >> 5;
            int k = li & 31;
            Ash[k][m] = embs[(m0 + m) * DDIM + kk + k];
            Bsh[k][m] = embs[(n0 + m) * DDIM + kk + k];
        }
        __syncthreads();
#pragma unroll
        for (int k = 0; k < 32; k++) {
            float2 a = *(const float2*)&Ash[k][2 * ty];
            float2 b = *(const float2*)&Bsh[k][2 * tx];
            a00 += a.x * b.x; a01 += a.x * b.y;
            a10 += a.y * b.x; a11 += a.y * b.y;
        }
        __syncthreads();
    }

    const int row0 = m0 + 2 * ty;
    const int col0 = n0 + 2 * tx;
    *(float2*)&g_dot[row0 * NROWS + col0]       = make_float2(a00, a01);
    *(float2*)&g_dot[(row0 + 1) * NROWS + col0] = make_float2(a10, a11);

    // Diagonal tiles: emit inverse norms (a00 = d[r][r], a11 = d[r+1][r+1])
    if (bx == by && tx == ty) {
        g_inv[row0]     = 1.0f / fmaxf(sqrtf(a00), 1e-8f);
        g_inv[row0 + 1] = 1.0f / fmaxf(sqrtf(a11), 1e-8f);
    }

    if (blockIdx.x == 0) {
        // Dtype probe: odd int32 positions within the first 2048 bytes.
        // int64 layout -> all zero (high words of values in [0,64)).
        // int32 layout -> real class IDs, essentially never all zero.
        __shared__ int fl;
        if (tid == 0) { fl = 0; *out = 0.0f; }
        __syncthreads();
        if (idx32view[2 * tid + 1] != 0) atomicOr(&fl, 1);
        __syncthreads();
        if (tid == 0) g_idx32 = fl;
    }
}

// ---------------------------------------------------------------------------
// Kernel 2: triplet sum, warp-per-anchor. 64 blocks x 256 threads.
// Anchor mapping transposed for balance: anchor = w*64 + blockIdx.x.
// Each lane caches its <=16 cos values in registers (adjusted: c+1 for valid
// negatives, -1e30 sentinel otherwise), positives compacted to shared via
// uniform ballot loop. Hot loop = np x 16 unrolled register fmax ops.
// One atomicAdd per BLOCK (64 total).
// ---------------------------------------------------------------------------
__global__ void triplet_kernel(const void* __restrict__ idxraw,
                               float* __restrict__ out) {
    const int tid  = threadIdx.x;
    const int w    = tid >> 5;            // warp 0..7
    const int lane = tid & 31;

    __shared__ float s_inv[NROWS];
    __shared__ int   s_cls[NROWS];
    __shared__ float s_pos[8][32];        // positives per anchor (~4 expected)
    __shared__ float s_wsum[8];

    const int is32 = g_idx32;
    const int* __restrict__ i32 = (const int*)idxraw;
    const long long* __restrict__ i64 = (const long long*)idxraw;

#pragma unroll
    for (int e = 0; e < 2; e++) {
        int r = tid + e * 256;
        s_inv[r] = g_inv[r];                       // coalesced
        s_cls[r] = is32 ? i32[r] : (int)i64[r];    // coalesced
    }
    __syncthreads();

    const int i = w * 64 + blockIdx.x;    // balanced anchor mapping
    const int   ci   = s_cls[i];
    const float invi = s_inv[i];
    const float* __restrict__ rowi = &g_dot[i * NROWS];

    // Single pass: fill register slots + compact positives (uniform 16 iters,
    // every lane hits every ballot -> no divergence hazard).
    float a[16];
    int np = 0;
#pragma unroll
    for (int slot = 0; slot < 16; slot++) {
        int j = i + 1 + lane + slot * 32;
        bool valid = (j < NROWS);
        float c = 0.0f;
        bool match = false;
        if (valid) {
            c = rowi[j] * invi * s_inv[j];
            match = (s_cls[j] == ci);
        }
        unsigned mask = __ballot_sync(0xffffffffu, match);
        if (match) {
            int off = np + __popc(mask & ((1u << lane) - 1u));
            if (off < 32) s_pos[w][off] = c;
        }
        np += __popc(mask);
        a[slot] = (valid && !match) ? (c + 1.0f) : -1e30f;  // sentinel -> 0 contribution
    }
    if (np > 32) np = 32;   // capacity guard (expected np ~ 4)
    __syncwarp();

    // Hot loop: np broadcast-LDS reads, 16 unrolled register fmax each.
    float s0 = 0.f, s1 = 0.f;
    for (int p = 0; p < np; p++) {
        float bp = s_pos[w][p];
#pragma unroll
        for (int slot = 0; slot < 16; slot += 2) {
            s0 += fmaxf(a[slot]     - bp, 0.0f);
            s1 += fmaxf(a[slot + 1] - bp, 0.0f);
        }
    }
    float s = s0 + s1;

#pragma unroll
    for (int o = 16; o; o >>= 1) s += __shfl_xor_sync(0xffffffffu, s, o);
    if (lane == 0) s_wsum[w] = s;
    __syncthreads();

    if (tid < 8) {
        float v = s_wsum[tid];
#pragma unroll
        for (int o = 4; o; o >>= 1) v += __shfl_xor_sync(0xffu, v, o);
        if (tid == 0) atomicAdd(out, v);   // one atomic per block (64 total)
    }
}

extern "C" void kernel_launch(void* const* d_in, const int* in_sizes, int n_in,
                              void* d_out, int out_size) {
    const float* embs = (const float*)d_in[0];
    const void*  indices = d_in[1];
    float* out = (float*)d_out;

    dot_kernel<<<UPPER_TILES, 256>>>(embs, (const int*)indices, out);
    triplet_kernel<<<64, 256>>>(indices, out);
}